// round 12
// baseline (speedup 1.0000x reference)
#include <cuda_runtime.h>
#include <cuda_fp16.h>
#include <cstdint>
#include <math.h>

// SimCLR InfoNCE + ranking metrics. R12: single-term fp16 HMMA GEMM
// (sim ~= h16.h16^T, fp32 accum) + fused epilogue; borderline rank
// comparisons row-bucketed and resolved by an exact-fp32 recheck kernel
// that also performs the final reduction (last-block pattern).

namespace {
constexpr int   N      = 8192;
constexpr int   D      = 512;
constexpr int   HALF   = 4096;
constexpr float TEMP   = 0.07f;
constexpr int   BM     = 128;
constexpr int   BK     = 64;
constexpr int   KSTEPS = 8;                   // 512/64
constexpr int   STAGES = 3;
constexpr int   LDK    = 72;                  // fp16 row stride (144B)
constexpr int   BUFB   = BM * LDK * 2;        // 18432 B per matrix per stage
constexpr int   STAGEB = 2 * BUFB;            // 36864
constexpr int   SMEM_DYN = STAGES * STAGEB;   // 110592 -> 2 CTA/SM
constexpr int   NTILES = 64 * 65 / 2;         // 2080
constexpr float DELTA  = 1e-4f;               // ~11 sigma of fp16 dot error
constexpr int   BINCAP = 32;                  // per-row borderline bin capacity
constexpr int   BCAP   = 1 << 20;             // overflow list capacity
constexpr int   REC_BLOCKS = N / 8;           // 1024 blocks x 8 warps = 1 warp/row
}

// ---- device scratch ----
__device__ float    g_fn[N * D];
__device__ __half   g_h16[N * D];
__device__ float    g_pos[N];
__device__ float    g_rowS[N];
__device__ int      g_rowC[N];
__device__ int      g_bcnt[N];                // borderline count per row
__device__ uint16_t g_bj[N * BINCAP];         // borderline js per row
__device__ uint32_t g_border[BCAP];           // overflow (i<<13)|j
__device__ int      g_nBorder;
__device__ int      g_done;

__device__ __forceinline__ uint32_t smem_u32(const void* p) {
    uint32_t a;
    asm("{ .reg .u64 t; cvta.to.shared.u64 t, %1; cvt.u32.u64 %0, t; }" : "=r"(a) : "l"(p));
    return a;
}
#define CP16(sa, g) asm volatile("cp.async.cg.shared.global [%0], [%1], 16;" :: "r"(sa), "l"(g))
#define CP_COMMIT() asm volatile("cp.async.commit_group;")
#define CP_WAIT(n)  asm volatile("cp.async.wait_group %0;" :: "n"(n))
#define LDSM4(r0, r1, r2, r3, a)                                             \
    asm volatile("ldmatrix.sync.aligned.m8n8.x4.shared.b16 {%0,%1,%2,%3}, [%4];" \
                 : "=r"(r0), "=r"(r1), "=r"(r2), "=r"(r3) : "r"(a))
#define MMA16816(c, a, b0, b1)                                               \
    asm volatile("mma.sync.aligned.m16n8k16.row.col.f32.f16.f16.f32 "        \
                 "{%0,%1,%2,%3}, {%4,%5,%6,%7}, {%8,%9}, {%0,%1,%2,%3};"     \
                 : "+f"((c)[0]), "+f"((c)[1]), "+f"((c)[2]), "+f"((c)[3])    \
                 : "r"((a)[0]), "r"((a)[1]), "r"((a)[2]), "r"((a)[3]),       \
                   "r"(b0), "r"(b1))

__device__ __forceinline__ void push_border(int i, int j) {
    int slot = atomicAdd(&g_bcnt[i], 1);
    if (slot < BINCAP) {
        g_bj[i * BINCAP + slot] = (uint16_t)j;
    } else {
        uint32_t idx = (uint32_t)atomicAdd(&g_nBorder, 1);
        if (idx < (uint32_t)BCAP) g_border[idx] = ((uint32_t)i << 13) | (uint32_t)j;
    }
}

// ---------------- small kernels ----------------
__global__ void k_norm(const float* __restrict__ f1, const float* __restrict__ f2) {
    const int row = blockIdx.x;
    const float* src = (row < HALF) ? (f1 + (size_t)row * D)
                                    : (f2 + (size_t)(row - HALF) * D);
    const int t = threadIdx.x;   // 128 threads x float4
    if (t == 0) {
        g_rowS[row] = 0.f; g_rowC[row] = 0; g_bcnt[row] = 0;
        if (row == 0) { g_nBorder = 0; g_done = 0; }
    }
    float4 v = reinterpret_cast<const float4*>(src)[t];
    float ss = v.x * v.x + v.y * v.y + v.z * v.z + v.w * v.w;
#pragma unroll
    for (int o = 16; o; o >>= 1) ss += __shfl_xor_sync(0xffffffffu, ss, o);
    __shared__ float ws[4];
    if ((t & 31) == 0) ws[t >> 5] = ss;
    __syncthreads();
    const float inv = 1.0f / fmaxf(sqrtf(ws[0] + ws[1] + ws[2] + ws[3]), 1e-8f);
    float x[4] = { v.x * inv, v.y * inv, v.z * inv, v.w * inv };
    reinterpret_cast<float4*>(g_fn + (size_t)row * D)[t] =
        make_float4(x[0], x[1], x[2], x[3]);
    __half2 h0 = __floats2half2_rn(x[0], x[1]);
    __half2 h1 = __floats2half2_rn(x[2], x[3]);
    reinterpret_cast<__half2*>(g_h16 + (size_t)row * D)[t * 2]     = h0;
    reinterpret_cast<__half2*>(g_h16 + (size_t)row * D)[t * 2 + 1] = h1;
}

__global__ void k_pos() {
    const int row  = blockIdx.x * 8 + (threadIdx.x >> 5);
    const int lane = threadIdx.x & 31;
    const int prow = (row + HALF) & (N - 1);
    const float4* a = reinterpret_cast<const float4*>(g_fn + (size_t)row * D);
    const float4* b = reinterpret_cast<const float4*>(g_fn + (size_t)prow * D);
    float s = 0.f;
#pragma unroll
    for (int q = 0; q < 4; q++) {
        float4 x = a[lane + q * 32], y = b[lane + q * 32];
        s += x.x * y.x + x.y * y.y + x.z * y.z + x.w * y.w;
    }
#pragma unroll
    for (int o = 16; o; o >>= 1) s += __shfl_xor_sync(0xffffffffu, s, o);
    if (lane == 0) g_pos[row] = s;
}

// ---------------- main: triangular-tile fp16 HMMA GEMM + fused epilogue ----------------
__global__ void __launch_bounds__(256, 2) k_main() {
    extern __shared__ __align__(16) char dsm[];

    const int t = blockIdx.x;
    int bi = (int)((sqrtf(8.0f * (float)t + 1.0f) - 1.0f) * 0.5f);
    while ((bi + 1) * (bi + 2) / 2 <= t) ++bi;
    while (bi * (bi + 1) / 2 > t) --bi;
    const int bj = t - bi * (bi + 1) / 2;
    const bool offd = (bi != bj);
    const int rowBase = bi * BM;
    const int colBase = bj * BM;

    const int tid  = threadIdx.x;
    const int l    = tid & 31;
    const int wid  = tid >> 5;
    const int warpM = wid & 1;
    const int warpN = wid >> 1;
    const float invT = 1.0f / TEMP;

    uint32_t aBufU[STAGES], bBufU[STAGES];
#pragma unroll
    for (int s = 0; s < STAGES; s++) {
        aBufU[s] = smem_u32(dsm + s * STAGEB);
        bBufU[s] = aBufU[s] + BUFB;
    }
    uint32_t dstOff[4];
    int gRow[4], gQ[4];
#pragma unroll
    for (int i = 0; i < 4; i++) {
        int c = i * 256 + tid;
        gRow[i] = c >> 3; gQ[i] = c & 7;
        dstOff[i] = (uint32_t)(gRow[i] * (LDK * 2) + gQ[i] * 16);
    }

    const uint32_t aFragOff =
        (uint32_t)(((warpM * 64 + (l & 15)) * LDK + (l >> 4) * 8) * 2);
    const uint32_t bFragOff =
        (uint32_t)(((warpN * 32 + (l & 7) + (l >> 4) * 8) * LDK + ((l >> 3) & 1) * 8) * 2);

    float acc[4][4][4];
#pragma unroll
    for (int mt = 0; mt < 4; mt++)
#pragma unroll
        for (int nt = 0; nt < 4; nt++)
#pragma unroll
            for (int r = 0; r < 4; r++) acc[mt][nt][r] = 0.f;

    auto issue = [&](int g, int b) {
        const int kb = g * BK;
#pragma unroll
        for (int i = 0; i < 4; i++) {
            CP16(aBufU[b] + dstOff[i],
                 g_h16 + (size_t)(rowBase + gRow[i]) * D + kb + gQ[i] * 8);
            CP16(bBufU[b] + dstOff[i],
                 g_h16 + (size_t)(colBase + gRow[i]) * D + kb + gQ[i] * 8);
        }
    };

    issue(0, 0); CP_COMMIT();
    issue(1, 1); CP_COMMIT();

#pragma unroll
    for (int g = 0; g < KSTEPS; ++g) {
        const int b = g % STAGES;
        CP_WAIT(1);
        __syncthreads();
        if (g + 2 < KSTEPS) issue(g + 2, (g + 2) % STAGES);
        CP_COMMIT();

        const uint32_t ua = aBufU[b], ub = bBufU[b];
        uint32_t bfr[2][2][4];
#pragma unroll
        for (int np = 0; np < 2; np++)
            LDSM4(bfr[0][np][0], bfr[0][np][1], bfr[0][np][2], bfr[0][np][3],
                  ub + bFragOff + (uint32_t)(np * 16 * LDK * 2));
#pragma unroll
        for (int ks = 0; ks < 4; ks++) {
            const int cur = ks & 1;
            if (ks < 3) {
#pragma unroll
                for (int np = 0; np < 2; np++)
                    LDSM4(bfr[cur ^ 1][np][0], bfr[cur ^ 1][np][1],
                          bfr[cur ^ 1][np][2], bfr[cur ^ 1][np][3],
                          ub + bFragOff + (uint32_t)(np * 16 * LDK * 2 + (ks + 1) * 32));
            }
#pragma unroll
            for (int mt = 0; mt < 4; mt++) {
                uint32_t afr[4];
                LDSM4(afr[0], afr[1], afr[2], afr[3],
                      ua + aFragOff + (uint32_t)(mt * 16 * LDK * 2 + ks * 32));
#pragma unroll
                for (int nt = 0; nt < 4; nt++)
                    MMA16816(acc[mt][nt], afr,
                             bfr[cur][nt >> 1][(nt & 1) * 2],
                             bfr[cur][nt >> 1][(nt & 1) * 2 + 1]);
            }
        }
    }

    // ---- fused epilogue ----
    float pvR[4][2]; int piR[4][2];
    float pvC[4][2]; int piC[4][2];
    float sR[4][2], sC[4][2];
    int   cR[4][2], cC[4][2];
#pragma unroll
    for (int mt = 0; mt < 4; mt++)
#pragma unroll
        for (int h = 0; h < 2; h++) {
            int row = rowBase + warpM * 64 + mt * 16 + (l >> 2) + h * 8;
            pvR[mt][h] = g_pos[row]; piR[mt][h] = (row + HALF) & (N - 1);
            sR[mt][h] = 0.f; cR[mt][h] = 0;
        }
#pragma unroll
    for (int nt = 0; nt < 4; nt++)
#pragma unroll
        for (int e = 0; e < 2; e++) {
            int col = colBase + warpN * 32 + nt * 8 + (l & 3) * 2 + e;
            pvC[nt][e] = g_pos[col]; piC[nt][e] = (col + HALF) & (N - 1);
            sC[nt][e] = 0.f; cC[nt][e] = 0;
        }

#pragma unroll
    for (int mt = 0; mt < 4; mt++)
#pragma unroll
        for (int nt = 0; nt < 4; nt++)
#pragma unroll
            for (int r = 0; r < 4; r++) {
                const int h = r >> 1, e = r & 1;
                const int row = rowBase + warpM * 64 + mt * 16 + (l >> 2) + h * 8;
                const int col = colBase + warpN * 32 + nt * 8 + (l & 3) * 2 + e;
                const float sim = acc[mt][nt][r];
                const float ex  = __expf((sim - 1.0f) * invT);
                if (col != row) {
                    sR[mt][h] += ex;
                    if (col != piR[mt][h]) {
                        float d = sim - pvR[mt][h];
                        if (d > DELTA) cR[mt][h]++;
                        else if (d >= -DELTA) push_border(row, col);
                    }
                }
                if (offd) {
                    sC[nt][e] += ex;
                    if (row != piC[nt][e]) {
                        float d = sim - pvC[nt][e];
                        if (d > DELTA) cC[nt][e]++;
                        else if (d >= -DELTA) push_border(col, row);
                    }
                }
            }

#pragma unroll
    for (int mt = 0; mt < 4; mt++)
#pragma unroll
        for (int h = 0; h < 2; h++) {
            float s = sR[mt][h]; int c = cR[mt][h];
            s += __shfl_xor_sync(0xffffffffu, s, 1);
            s += __shfl_xor_sync(0xffffffffu, s, 2);
            c += __shfl_xor_sync(0xffffffffu, c, 1);
            c += __shfl_xor_sync(0xffffffffu, c, 2);
            if ((l & 3) == 0) {
                int row = rowBase + warpM * 64 + mt * 16 + (l >> 2) + h * 8;
                atomicAdd(&g_rowS[row], s);
                atomicAdd(&g_rowC[row], c);
            }
        }
    if (offd) {
#pragma unroll
        for (int nt = 0; nt < 4; nt++)
#pragma unroll
            for (int e = 0; e < 2; e++) {
                float s = sC[nt][e]; int c = cC[nt][e];
                s += __shfl_xor_sync(0xffffffffu, s, 4);
                s += __shfl_xor_sync(0xffffffffu, s, 8);
                s += __shfl_xor_sync(0xffffffffu, s, 16);
                c += __shfl_xor_sync(0xffffffffu, c, 4);
                c += __shfl_xor_sync(0xffffffffu, c, 8);
                c += __shfl_xor_sync(0xffffffffu, c, 16);
                if (l < 4) {
                    int col = colBase + warpN * 32 + nt * 8 + (l & 3) * 2 + e;
                    atomicAdd(&g_rowS[col], s);
                    atomicAdd(&g_rowC[col], c);
                }
            }
    }
}

// Row-bucketed exact recheck + final reduction (last-block pattern).
// One warp per row: row i held in 16 regs/lane; stream only column rows.
__global__ void __launch_bounds__(256) k_recheck(float* __restrict__ out) {
    const int wid  = threadIdx.x >> 5;
    const int lane = threadIdx.x & 31;
    const int i    = blockIdx.x * 8 + wid;
    const float invT = 1.0f / TEMP;

    {
        const int nb = min(g_bcnt[i], BINCAP);
        if (nb > 0) {
            const float4* a = reinterpret_cast<const float4*>(g_fn + (size_t)i * D);
            float4 av[4];
#pragma unroll
            for (int q = 0; q < 4; q++) av[q] = a[lane + q * 32];
            const float pv = g_pos[i];
            int cnt = 0;
            for (int b = 0; b < nb; b++) {
                const int j = g_bj[i * BINCAP + b];
                const float4* bb = reinterpret_cast<const float4*>(g_fn + (size_t)j * D);
                float s = 0.f;
#pragma unroll
                for (int q = 0; q < 4; q++) {
                    float4 y = bb[lane + q * 32];
                    s = fmaf(av[q].x, y.x, fmaf(av[q].y, y.y,
                        fmaf(av[q].z, y.z, fmaf(av[q].w, y.w, s))));
                }
#pragma unroll
                for (int o = 16; o; o >>= 1) s += __shfl_xor_sync(0xffffffffu, s, o);
                if (s > pv) cnt++;
            }
            if (lane == 0 && cnt > 0) atomicAdd(&g_rowC[i], cnt);
        }
    }

    // overflow list (rare): grid-stride, one warp per pair
    {
        const int nWarps = gridDim.x * 8;
        const int w = blockIdx.x * 8 + wid;
        const int cnt = min(g_nBorder, BCAP);
        for (int e = w; e < cnt; e += nWarps) {
            const uint32_t p = g_border[e];
            const int ii = (int)(p >> 13);
            const int jj = (int)(p & 8191u);
            const float4* a = reinterpret_cast<const float4*>(g_fn + (size_t)ii * D);
            const float4* b = reinterpret_cast<const float4*>(g_fn + (size_t)jj * D);
            float s = 0.f;
#pragma unroll
            for (int q = 0; q < 4; q++) {
                float4 x = a[lane + q * 32], y = b[lane + q * 32];
                s = fmaf(x.x, y.x, fmaf(x.y, y.y, fmaf(x.z, y.z, fmaf(x.w, y.w, s))));
            }
#pragma unroll
            for (int o = 16; o; o >>= 1) s += __shfl_xor_sync(0xffffffffu, s, o);
            if (lane == 0 && s > g_pos[ii]) atomicAdd(&g_rowC[ii], 1);
        }
    }

    // ---- last block performs the final reduction ----
    __shared__ int sIsLast;
    __syncthreads();
    if (threadIdx.x == 0) {
        __threadfence();
        sIsLast = (atomicAdd(&g_done, 1) == gridDim.x - 1) ? 1 : 0;
    }
    __syncthreads();
    if (!sIsLast) return;
    __threadfence();  // acquire: see all blocks' g_rowC updates

    double accT = 0.0; int t1 = 0, t5 = 0; long long rk = 0;
    for (int r = threadIdx.x; r < N; r += 256) {
        const float sv = g_rowS[r];
        const int   cv = g_rowC[r];
        accT += (double)((logf(sv) + invT) - g_pos[r] * invT);
        t1 += (cv == 0);
        t5 += (cv < 5);
        rk += cv;
    }
#pragma unroll
    for (int o = 16; o; o >>= 1) {
        accT += __shfl_xor_sync(0xffffffffu, accT, o);
        t1   += __shfl_xor_sync(0xffffffffu, t1, o);
        t5   += __shfl_xor_sync(0xffffffffu, t5, o);
        rk   += __shfl_xor_sync(0xffffffffu, rk, o);
    }
    __shared__ double sT[8];
    __shared__ int sT1[8], sT5[8];
    __shared__ long long sRk[8];
    if (lane == 0) { sT[wid] = accT; sT1[wid] = t1; sT5[wid] = t5; sRk[wid] = rk; }
    __syncthreads();
    if (threadIdx.x == 0) {
        double a = 0.0; int b = 0, c = 0; long long d2 = 0;
#pragma unroll
        for (int q = 0; q < 8; q++) { a += sT[q]; b += sT1[q]; c += sT5[q]; d2 += sRk[q]; }
        out[0] = (float)(a / (double)N);
        out[1] = (float)b / (float)N;
        out[2] = (float)c / (float)N;
        out[3] = 1.0f + (float)((double)d2 / (double)N);
    }
}

extern "C" void kernel_launch(void* const* d_in, const int* in_sizes, int n_in,
                              void* d_out, int out_size) {
    (void)in_sizes; (void)n_in; (void)out_size;
    const float* f1 = (const float*)d_in[0];
    const float* f2 = (const float*)d_in[1];
    float* out = (float*)d_out;

    cudaFuncSetAttribute(k_main, cudaFuncAttributeMaxDynamicSharedMemorySize, SMEM_DYN);

    k_norm<<<N, 128>>>(f1, f2);
    k_pos<<<N / 8, 256>>>();
    k_main<<<NTILES, 256, SMEM_DYN>>>();
    k_recheck<<<REC_BLOCKS, 256>>>(out);
}

// round 13
// speedup vs baseline: 1.0489x; 1.0489x over previous
#include <cuda_runtime.h>
#include <cuda_fp16.h>
#include <cstdint>
#include <math.h>

// SimCLR InfoNCE + ranking metrics. R13: R11 configuration (best: 212us)
// with k_merge/k_final fused into k_recheck via last-block reduction.
//   k_main: single-term fp16 HMMA GEMM, BK=64, 3-stage cp.async ring,
//   triangular tiles, fused exp/rank epilogue, flat borderline list.
//   k_recheck: one warp per borderline pair (L2-BW floor) + final stats.

namespace {
constexpr int   N      = 8192;
constexpr int   D      = 512;
constexpr int   HALF   = 4096;
constexpr float TEMP   = 0.07f;
constexpr int   BM     = 128;
constexpr int   BK     = 64;
constexpr int   KSTEPS = 8;                   // 512/64
constexpr int   STAGES = 3;
constexpr int   LDK    = 72;                  // fp16 row stride (144B)
constexpr int   BUFB   = BM * LDK * 2;        // 18432 B per matrix per stage
constexpr int   STAGEB = 2 * BUFB;            // 36864
constexpr int   SMEM_DYN = STAGES * STAGEB;   // 110592 -> 2 CTA/SM
constexpr int   NTILES = 64 * 65 / 2;         // 2080
constexpr float DELTA  = 1e-4f;               // ~11 sigma of fp16 dot error
constexpr int   BCAP   = 1 << 21;             // borderline list capacity
constexpr int   REC_BLOCKS = 592;             // 4736 warps (grid-stride)
}

// ---- device scratch ----
__device__ float    g_fn[N * D];
__device__ __half   g_h16[N * D];
__device__ float    g_pos[N];
__device__ float    g_rowS[N];
__device__ int      g_rowC[N];
__device__ uint32_t g_border[BCAP];           // (i<<13)|j
__device__ int      g_nBorder;
__device__ int      g_done;

__device__ __forceinline__ uint32_t smem_u32(const void* p) {
    uint32_t a;
    asm("{ .reg .u64 t; cvta.to.shared.u64 t, %1; cvt.u32.u64 %0, t; }" : "=r"(a) : "l"(p));
    return a;
}
#define CP16(sa, g) asm volatile("cp.async.cg.shared.global [%0], [%1], 16;" :: "r"(sa), "l"(g))
#define CP_COMMIT() asm volatile("cp.async.commit_group;")
#define CP_WAIT(n)  asm volatile("cp.async.wait_group %0;" :: "n"(n))
#define LDSM4(r0, r1, r2, r3, a)                                             \
    asm volatile("ldmatrix.sync.aligned.m8n8.x4.shared.b16 {%0,%1,%2,%3}, [%4];" \
                 : "=r"(r0), "=r"(r1), "=r"(r2), "=r"(r3) : "r"(a))
#define MMA16816(c, a, b0, b1)                                               \
    asm volatile("mma.sync.aligned.m16n8k16.row.col.f32.f16.f16.f32 "        \
                 "{%0,%1,%2,%3}, {%4,%5,%6,%7}, {%8,%9}, {%0,%1,%2,%3};"     \
                 : "+f"((c)[0]), "+f"((c)[1]), "+f"((c)[2]), "+f"((c)[3])    \
                 : "r"((a)[0]), "r"((a)[1]), "r"((a)[2]), "r"((a)[3]),       \
                   "r"(b0), "r"(b1))

__device__ __forceinline__ void push_border(int i, int j) {
    uint32_t idx = (uint32_t)atomicAdd(&g_nBorder, 1);
    if (idx < (uint32_t)BCAP) g_border[idx] = ((uint32_t)i << 13) | (uint32_t)j;
}

// ---------------- small kernels ----------------
__global__ void k_norm(const float* __restrict__ f1, const float* __restrict__ f2) {
    const int row = blockIdx.x;
    const float* src = (row < HALF) ? (f1 + (size_t)row * D)
                                    : (f2 + (size_t)(row - HALF) * D);
    const int t = threadIdx.x;   // 128 threads x float4
    if (t == 0) {
        g_rowS[row] = 0.f; g_rowC[row] = 0;
        if (row == 0) { g_nBorder = 0; g_done = 0; }
    }
    float4 v = reinterpret_cast<const float4*>(src)[t];
    float ss = v.x * v.x + v.y * v.y + v.z * v.z + v.w * v.w;
#pragma unroll
    for (int o = 16; o; o >>= 1) ss += __shfl_xor_sync(0xffffffffu, ss, o);
    __shared__ float ws[4];
    if ((t & 31) == 0) ws[t >> 5] = ss;
    __syncthreads();
    const float inv = 1.0f / fmaxf(sqrtf(ws[0] + ws[1] + ws[2] + ws[3]), 1e-8f);
    float x[4] = { v.x * inv, v.y * inv, v.z * inv, v.w * inv };
    reinterpret_cast<float4*>(g_fn + (size_t)row * D)[t] =
        make_float4(x[0], x[1], x[2], x[3]);
    __half2 h0 = __floats2half2_rn(x[0], x[1]);
    __half2 h1 = __floats2half2_rn(x[2], x[3]);
    reinterpret_cast<__half2*>(g_h16 + (size_t)row * D)[t * 2]     = h0;
    reinterpret_cast<__half2*>(g_h16 + (size_t)row * D)[t * 2 + 1] = h1;
}

__global__ void k_pos() {
    const int row  = blockIdx.x * 8 + (threadIdx.x >> 5);
    const int lane = threadIdx.x & 31;
    const int prow = (row + HALF) & (N - 1);
    const float4* a = reinterpret_cast<const float4*>(g_fn + (size_t)row * D);
    const float4* b = reinterpret_cast<const float4*>(g_fn + (size_t)prow * D);
    float s = 0.f;
#pragma unroll
    for (int q = 0; q < 4; q++) {
        float4 x = a[lane + q * 32], y = b[lane + q * 32];
        s += x.x * y.x + x.y * y.y + x.z * y.z + x.w * y.w;
    }
#pragma unroll
    for (int o = 16; o; o >>= 1) s += __shfl_xor_sync(0xffffffffu, s, o);
    if (lane == 0) g_pos[row] = s;
}

// ---------------- main: triangular-tile fp16 HMMA GEMM + fused epilogue ----------------
__global__ void __launch_bounds__(256, 2) k_main() {
    extern __shared__ __align__(16) char dsm[];

    const int t = blockIdx.x;
    int bi = (int)((sqrtf(8.0f * (float)t + 1.0f) - 1.0f) * 0.5f);
    while ((bi + 1) * (bi + 2) / 2 <= t) ++bi;
    while (bi * (bi + 1) / 2 > t) --bi;
    const int bj = t - bi * (bi + 1) / 2;
    const bool offd = (bi != bj);
    const int rowBase = bi * BM;
    const int colBase = bj * BM;

    const int tid  = threadIdx.x;
    const int l    = tid & 31;
    const int wid  = tid >> 5;
    const int warpM = wid & 1;
    const int warpN = wid >> 1;
    const float invT = 1.0f / TEMP;

    uint32_t aBufU[STAGES], bBufU[STAGES];
#pragma unroll
    for (int s = 0; s < STAGES; s++) {
        aBufU[s] = smem_u32(dsm + s * STAGEB);
        bBufU[s] = aBufU[s] + BUFB;
    }
    uint32_t dstOff[4];
    int gRow[4], gQ[4];
#pragma unroll
    for (int i = 0; i < 4; i++) {
        int c = i * 256 + tid;
        gRow[i] = c >> 3; gQ[i] = c & 7;
        dstOff[i] = (uint32_t)(gRow[i] * (LDK * 2) + gQ[i] * 16);
    }

    const uint32_t aFragOff =
        (uint32_t)(((warpM * 64 + (l & 15)) * LDK + (l >> 4) * 8) * 2);
    const uint32_t bFragOff =
        (uint32_t)(((warpN * 32 + (l & 7) + (l >> 4) * 8) * LDK + ((l >> 3) & 1) * 8) * 2);

    float acc[4][4][4];
#pragma unroll
    for (int mt = 0; mt < 4; mt++)
#pragma unroll
        for (int nt = 0; nt < 4; nt++)
#pragma unroll
            for (int r = 0; r < 4; r++) acc[mt][nt][r] = 0.f;

    auto issue = [&](int g, int b) {
        const int kb = g * BK;
#pragma unroll
        for (int i = 0; i < 4; i++) {
            CP16(aBufU[b] + dstOff[i],
                 g_h16 + (size_t)(rowBase + gRow[i]) * D + kb + gQ[i] * 8);
            CP16(bBufU[b] + dstOff[i],
                 g_h16 + (size_t)(colBase + gRow[i]) * D + kb + gQ[i] * 8);
        }
    };

    issue(0, 0); CP_COMMIT();
    issue(1, 1); CP_COMMIT();

#pragma unroll
    for (int g = 0; g < KSTEPS; ++g) {
        const int b = g % STAGES;
        CP_WAIT(1);
        __syncthreads();
        if (g + 2 < KSTEPS) issue(g + 2, (g + 2) % STAGES);
        CP_COMMIT();

        const uint32_t ua = aBufU[b], ub = bBufU[b];
        uint32_t bfr[2][2][4];
#pragma unroll
        for (int np = 0; np < 2; np++)
            LDSM4(bfr[0][np][0], bfr[0][np][1], bfr[0][np][2], bfr[0][np][3],
                  ub + bFragOff + (uint32_t)(np * 16 * LDK * 2));
#pragma unroll
        for (int ks = 0; ks < 4; ks++) {
            const int cur = ks & 1;
            if (ks < 3) {
#pragma unroll
                for (int np = 0; np < 2; np++)
                    LDSM4(bfr[cur ^ 1][np][0], bfr[cur ^ 1][np][1],
                          bfr[cur ^ 1][np][2], bfr[cur ^ 1][np][3],
                          ub + bFragOff + (uint32_t)(np * 16 * LDK * 2 + (ks + 1) * 32));
            }
#pragma unroll
            for (int mt = 0; mt < 4; mt++) {
                uint32_t afr[4];
                LDSM4(afr[0], afr[1], afr[2], afr[3],
                      ua + aFragOff + (uint32_t)(mt * 16 * LDK * 2 + ks * 32));
#pragma unroll
                for (int nt = 0; nt < 4; nt++)
                    MMA16816(acc[mt][nt], afr,
                             bfr[cur][nt >> 1][(nt & 1) * 2],
                             bfr[cur][nt >> 1][(nt & 1) * 2 + 1]);
            }
        }
    }

    // ---- fused epilogue ----
    float pvR[4][2]; int piR[4][2];
    float pvC[4][2]; int piC[4][2];
    float sR[4][2], sC[4][2];
    int   cR[4][2], cC[4][2];
#pragma unroll
    for (int mt = 0; mt < 4; mt++)
#pragma unroll
        for (int h = 0; h < 2; h++) {
            int row = rowBase + warpM * 64 + mt * 16 + (l >> 2) + h * 8;
            pvR[mt][h] = g_pos[row]; piR[mt][h] = (row + HALF) & (N - 1);
            sR[mt][h] = 0.f; cR[mt][h] = 0;
        }
#pragma unroll
    for (int nt = 0; nt < 4; nt++)
#pragma unroll
        for (int e = 0; e < 2; e++) {
            int col = colBase + warpN * 32 + nt * 8 + (l & 3) * 2 + e;
            pvC[nt][e] = g_pos[col]; piC[nt][e] = (col + HALF) & (N - 1);
            sC[nt][e] = 0.f; cC[nt][e] = 0;
        }

#pragma unroll
    for (int mt = 0; mt < 4; mt++)
#pragma unroll
        for (int nt = 0; nt < 4; nt++)
#pragma unroll
            for (int r = 0; r < 4; r++) {
                const int h = r >> 1, e = r & 1;
                const int row = rowBase + warpM * 64 + mt * 16 + (l >> 2) + h * 8;
                const int col = colBase + warpN * 32 + nt * 8 + (l & 3) * 2 + e;
                const float sim = acc[mt][nt][r];
                const float ex  = __expf((sim - 1.0f) * invT);
                if (col != row) {
                    sR[mt][h] += ex;
                    if (col != piR[mt][h]) {
                        float d = sim - pvR[mt][h];
                        if (d > DELTA) cR[mt][h]++;
                        else if (d >= -DELTA) push_border(row, col);
                    }
                }
                if (offd) {
                    sC[nt][e] += ex;
                    if (row != piC[nt][e]) {
                        float d = sim - pvC[nt][e];
                        if (d > DELTA) cC[nt][e]++;
                        else if (d >= -DELTA) push_border(col, row);
                    }
                }
            }

#pragma unroll
    for (int mt = 0; mt < 4; mt++)
#pragma unroll
        for (int h = 0; h < 2; h++) {
            float s = sR[mt][h]; int c = cR[mt][h];
            s += __shfl_xor_sync(0xffffffffu, s, 1);
            s += __shfl_xor_sync(0xffffffffu, s, 2);
            c += __shfl_xor_sync(0xffffffffu, c, 1);
            c += __shfl_xor_sync(0xffffffffu, c, 2);
            if ((l & 3) == 0) {
                int row = rowBase + warpM * 64 + mt * 16 + (l >> 2) + h * 8;
                atomicAdd(&g_rowS[row], s);
                atomicAdd(&g_rowC[row], c);
            }
        }
    if (offd) {
#pragma unroll
        for (int nt = 0; nt < 4; nt++)
#pragma unroll
            for (int e = 0; e < 2; e++) {
                float s = sC[nt][e]; int c = cC[nt][e];
                s += __shfl_xor_sync(0xffffffffu, s, 4);
                s += __shfl_xor_sync(0xffffffffu, s, 8);
                s += __shfl_xor_sync(0xffffffffu, s, 16);
                c += __shfl_xor_sync(0xffffffffu, c, 4);
                c += __shfl_xor_sync(0xffffffffu, c, 8);
                c += __shfl_xor_sync(0xffffffffu, c, 16);
                if (l < 4) {
                    int col = colBase + warpN * 32 + nt * 8 + (l & 3) * 2 + e;
                    atomicAdd(&g_rowS[col], s);
                    atomicAdd(&g_rowC[col], c);
                }
            }
    }
}

// Flat exact recheck (L2-BW floor) + fused final reduction (last block).
__global__ void __launch_bounds__(256) k_recheck(float* __restrict__ out) {
    const int wid  = threadIdx.x >> 5;
    const int lane = threadIdx.x & 31;
    const float invT = 1.0f / TEMP;

    {
        const int nWarps = gridDim.x * 8;
        const int w = blockIdx.x * 8 + wid;
        const int cnt = min(g_nBorder, BCAP);
        for (int e = w; e < cnt; e += nWarps) {
            const uint32_t p = g_border[e];
            const int i = (int)(p >> 13);
            const int j = (int)(p & 8191u);
            const float4* a = reinterpret_cast<const float4*>(g_fn + (size_t)i * D);
            const float4* b = reinterpret_cast<const float4*>(g_fn + (size_t)j * D);
            float s = 0.f;
#pragma unroll
            for (int q = 0; q < 4; q++) {
                float4 x = a[lane + q * 32], y = b[lane + q * 32];
                s = fmaf(x.x, y.x, fmaf(x.y, y.y, fmaf(x.z, y.z, fmaf(x.w, y.w, s))));
            }
#pragma unroll
            for (int o = 16; o; o >>= 1) s += __shfl_xor_sync(0xffffffffu, s, o);
            if (lane == 0 && s > g_pos[i]) atomicAdd(&g_rowC[i], 1);
        }
    }

    // ---- last block performs the final reduction ----
    __shared__ int sIsLast;
    __syncthreads();
    if (threadIdx.x == 0) {
        __threadfence();
        sIsLast = (atomicAdd(&g_done, 1) == gridDim.x - 1) ? 1 : 0;
    }
    __syncthreads();
    if (!sIsLast) return;
    __threadfence();  // acquire: see all blocks' g_rowC updates

    double accT = 0.0; int t1 = 0, t5 = 0; long long rk = 0;
    for (int r = threadIdx.x; r < N; r += 256) {
        const float sv = g_rowS[r];
        const int   cv = g_rowC[r];
        accT += (double)((logf(sv) + invT) - g_pos[r] * invT);
        t1 += (cv == 0);
        t5 += (cv < 5);
        rk += cv;
    }
#pragma unroll
    for (int o = 16; o; o >>= 1) {
        accT += __shfl_xor_sync(0xffffffffu, accT, o);
        t1   += __shfl_xor_sync(0xffffffffu, t1, o);
        t5   += __shfl_xor_sync(0xffffffffu, t5, o);
        rk   += __shfl_xor_sync(0xffffffffu, rk, o);
    }
    __shared__ double sT[8];
    __shared__ int sT1[8], sT5[8];
    __shared__ long long sRk[8];
    if (lane == 0) { sT[wid] = accT; sT1[wid] = t1; sT5[wid] = t5; sRk[wid] = rk; }
    __syncthreads();
    if (threadIdx.x == 0) {
        double a = 0.0; int b = 0, c = 0; long long d2 = 0;
#pragma unroll
        for (int q = 0; q < 8; q++) { a += sT[q]; b += sT1[q]; c += sT5[q]; d2 += sRk[q]; }
        out[0] = (float)(a / (double)N);
        out[1] = (float)b / (float)N;
        out[2] = (float)c / (float)N;
        out[3] = 1.0f + (float)((double)d2 / (double)N);
    }
}

extern "C" void kernel_launch(void* const* d_in, const int* in_sizes, int n_in,
                              void* d_out, int out_size) {
    (void)in_sizes; (void)n_in; (void)out_size;
    const float* f1 = (const float*)d_in[0];
    const float* f2 = (const float*)d_in[1];
    float* out = (float*)d_out;

    cudaFuncSetAttribute(k_main, cudaFuncAttributeMaxDynamicSharedMemorySize, SMEM_DYN);

    k_norm<<<N, 128>>>(f1, f2);
    k_pos<<<N / 8, 256>>>();
    k_main<<<NTILES, 256, SMEM_DYN>>>();
    k_recheck<<<REC_BLOCKS, 256>>>(out);
}

// round 14
// speedup vs baseline: 1.1775x; 1.1226x over previous
#include <cuda_runtime.h>
#include <cuda_fp16.h>
#include <cstdint>
#include <math.h>

// SimCLR InfoNCE + ranking metrics. R14: R11 configuration (best: 212us)
// with DELTA tightened 1e-4 -> 6e-5 (5 sigma of fp16 dot error; ~40% fewer
// borderline pairs) and k_final fused into k_merge (last-block pattern).

namespace {
constexpr int   N      = 8192;
constexpr int   D      = 512;
constexpr int   HALF   = 4096;
constexpr float TEMP   = 0.07f;
constexpr int   BM     = 128;
constexpr int   BK     = 64;
constexpr int   KSTEPS = 8;                   // 512/64
constexpr int   STAGES = 3;
constexpr int   LDK    = 72;                  // fp16 row stride (144B)
constexpr int   BUFB   = BM * LDK * 2;        // 18432 B per matrix per stage
constexpr int   STAGEB = 2 * BUFB;            // 36864
constexpr int   SMEM_DYN = STAGES * STAGEB;   // 110592 -> 2 CTA/SM
constexpr int   NTILES = 64 * 65 / 2;         // 2080
constexpr float DELTA  = 6e-5f;               // 5 sigma of fp16 dot error
constexpr int   BCAP   = 1 << 21;             // borderline list capacity
constexpr int   REC_BLOCKS = 592;
}

// ---- device scratch ----
__device__ float    g_fn[N * D];
__device__ __half   g_h16[N * D];
__device__ float    g_pos[N];
__device__ float    g_rowS[N];
__device__ int      g_rowC[N];
__device__ uint32_t g_border[BCAP];           // (i<<13)|j
__device__ int      g_nBorder;
__device__ int      g_done;
__device__ double   g_nll;
__device__ int      g_top1;
__device__ int      g_top5;
__device__ unsigned long long g_rank;

__device__ __forceinline__ uint32_t smem_u32(const void* p) {
    uint32_t a;
    asm("{ .reg .u64 t; cvta.to.shared.u64 t, %1; cvt.u32.u64 %0, t; }" : "=r"(a) : "l"(p));
    return a;
}
#define CP16(sa, g) asm volatile("cp.async.cg.shared.global [%0], [%1], 16;" :: "r"(sa), "l"(g))
#define CP_COMMIT() asm volatile("cp.async.commit_group;")
#define CP_WAIT(n)  asm volatile("cp.async.wait_group %0;" :: "n"(n))
#define LDSM4(r0, r1, r2, r3, a)                                             \
    asm volatile("ldmatrix.sync.aligned.m8n8.x4.shared.b16 {%0,%1,%2,%3}, [%4];" \
                 : "=r"(r0), "=r"(r1), "=r"(r2), "=r"(r3) : "r"(a))
#define MMA16816(c, a, b0, b1)                                               \
    asm volatile("mma.sync.aligned.m16n8k16.row.col.f32.f16.f16.f32 "        \
                 "{%0,%1,%2,%3}, {%4,%5,%6,%7}, {%8,%9}, {%0,%1,%2,%3};"     \
                 : "+f"((c)[0]), "+f"((c)[1]), "+f"((c)[2]), "+f"((c)[3])    \
                 : "r"((a)[0]), "r"((a)[1]), "r"((a)[2]), "r"((a)[3]),       \
                   "r"(b0), "r"(b1))

__device__ __forceinline__ void push_border(int i, int j) {
    uint32_t idx = (uint32_t)atomicAdd(&g_nBorder, 1);
    if (idx < (uint32_t)BCAP) g_border[idx] = ((uint32_t)i << 13) | (uint32_t)j;
}

// ---------------- small kernels ----------------
__global__ void k_norm(const float* __restrict__ f1, const float* __restrict__ f2) {
    const int row = blockIdx.x;
    const float* src = (row < HALF) ? (f1 + (size_t)row * D)
                                    : (f2 + (size_t)(row - HALF) * D);
    const int t = threadIdx.x;   // 128 threads x float4
    if (t == 0) {
        g_rowS[row] = 0.f; g_rowC[row] = 0;
        if (row == 0) {
            g_nBorder = 0; g_done = 0;
            g_nll = 0.0; g_top1 = 0; g_top5 = 0; g_rank = 0ull;
        }
    }
    float4 v = reinterpret_cast<const float4*>(src)[t];
    float ss = v.x * v.x + v.y * v.y + v.z * v.z + v.w * v.w;
#pragma unroll
    for (int o = 16; o; o >>= 1) ss += __shfl_xor_sync(0xffffffffu, ss, o);
    __shared__ float ws[4];
    if ((t & 31) == 0) ws[t >> 5] = ss;
    __syncthreads();
    const float inv = 1.0f / fmaxf(sqrtf(ws[0] + ws[1] + ws[2] + ws[3]), 1e-8f);
    float x[4] = { v.x * inv, v.y * inv, v.z * inv, v.w * inv };
    reinterpret_cast<float4*>(g_fn + (size_t)row * D)[t] =
        make_float4(x[0], x[1], x[2], x[3]);
    __half2 h0 = __floats2half2_rn(x[0], x[1]);
    __half2 h1 = __floats2half2_rn(x[2], x[3]);
    reinterpret_cast<__half2*>(g_h16 + (size_t)row * D)[t * 2]     = h0;
    reinterpret_cast<__half2*>(g_h16 + (size_t)row * D)[t * 2 + 1] = h1;
}

__global__ void k_pos() {
    const int row  = blockIdx.x * 8 + (threadIdx.x >> 5);
    const int lane = threadIdx.x & 31;
    const int prow = (row + HALF) & (N - 1);
    const float4* a = reinterpret_cast<const float4*>(g_fn + (size_t)row * D);
    const float4* b = reinterpret_cast<const float4*>(g_fn + (size_t)prow * D);
    float s = 0.f;
#pragma unroll
    for (int q = 0; q < 4; q++) {
        float4 x = a[lane + q * 32], y = b[lane + q * 32];
        s += x.x * y.x + x.y * y.y + x.z * y.z + x.w * y.w;
    }
#pragma unroll
    for (int o = 16; o; o >>= 1) s += __shfl_xor_sync(0xffffffffu, s, o);
    if (lane == 0) g_pos[row] = s;
}

// ---------------- main: triangular-tile fp16 HMMA GEMM + fused epilogue ----------------
__global__ void __launch_bounds__(256, 2) k_main() {
    extern __shared__ __align__(16) char dsm[];

    const int t = blockIdx.x;
    int bi = (int)((sqrtf(8.0f * (float)t + 1.0f) - 1.0f) * 0.5f);
    while ((bi + 1) * (bi + 2) / 2 <= t) ++bi;
    while (bi * (bi + 1) / 2 > t) --bi;
    const int bj = t - bi * (bi + 1) / 2;
    const bool offd = (bi != bj);
    const int rowBase = bi * BM;
    const int colBase = bj * BM;

    const int tid  = threadIdx.x;
    const int l    = tid & 31;
    const int wid  = tid >> 5;
    const int warpM = wid & 1;
    const int warpN = wid >> 1;
    const float invT = 1.0f / TEMP;

    uint32_t aBufU[STAGES], bBufU[STAGES];
#pragma unroll
    for (int s = 0; s < STAGES; s++) {
        aBufU[s] = smem_u32(dsm + s * STAGEB);
        bBufU[s] = aBufU[s] + BUFB;
    }
    uint32_t dstOff[4];
    int gRow[4], gQ[4];
#pragma unroll
    for (int i = 0; i < 4; i++) {
        int c = i * 256 + tid;
        gRow[i] = c >> 3; gQ[i] = c & 7;
        dstOff[i] = (uint32_t)(gRow[i] * (LDK * 2) + gQ[i] * 16);
    }

    const uint32_t aFragOff =
        (uint32_t)(((warpM * 64 + (l & 15)) * LDK + (l >> 4) * 8) * 2);
    const uint32_t bFragOff =
        (uint32_t)(((warpN * 32 + (l & 7) + (l >> 4) * 8) * LDK + ((l >> 3) & 1) * 8) * 2);

    float acc[4][4][4];
#pragma unroll
    for (int mt = 0; mt < 4; mt++)
#pragma unroll
        for (int nt = 0; nt < 4; nt++)
#pragma unroll
            for (int r = 0; r < 4; r++) acc[mt][nt][r] = 0.f;

    auto issue = [&](int g, int b) {
        const int kb = g * BK;
#pragma unroll
        for (int i = 0; i < 4; i++) {
            CP16(aBufU[b] + dstOff[i],
                 g_h16 + (size_t)(rowBase + gRow[i]) * D + kb + gQ[i] * 8);
            CP16(bBufU[b] + dstOff[i],
                 g_h16 + (size_t)(colBase + gRow[i]) * D + kb + gQ[i] * 8);
        }
    };

    issue(0, 0); CP_COMMIT();
    issue(1, 1); CP_COMMIT();

#pragma unroll
    for (int g = 0; g < KSTEPS; ++g) {
        const int b = g % STAGES;
        CP_WAIT(1);
        __syncthreads();
        if (g + 2 < KSTEPS) issue(g + 2, (g + 2) % STAGES);
        CP_COMMIT();

        const uint32_t ua = aBufU[b], ub = bBufU[b];
        uint32_t bfr[2][2][4];
#pragma unroll
        for (int np = 0; np < 2; np++)
            LDSM4(bfr[0][np][0], bfr[0][np][1], bfr[0][np][2], bfr[0][np][3],
                  ub + bFragOff + (uint32_t)(np * 16 * LDK * 2));
#pragma unroll
        for (int ks = 0; ks < 4; ks++) {
            const int cur = ks & 1;
            if (ks < 3) {
#pragma unroll
                for (int np = 0; np < 2; np++)
                    LDSM4(bfr[cur ^ 1][np][0], bfr[cur ^ 1][np][1],
                          bfr[cur ^ 1][np][2], bfr[cur ^ 1][np][3],
                          ub + bFragOff + (uint32_t)(np * 16 * LDK * 2 + (ks + 1) * 32));
            }
#pragma unroll
            for (int mt = 0; mt < 4; mt++) {
                uint32_t afr[4];
                LDSM4(afr[0], afr[1], afr[2], afr[3],
                      ua + aFragOff + (uint32_t)(mt * 16 * LDK * 2 + ks * 32));
#pragma unroll
                for (int nt = 0; nt < 4; nt++)
                    MMA16816(acc[mt][nt], afr,
                             bfr[cur][nt >> 1][(nt & 1) * 2],
                             bfr[cur][nt >> 1][(nt & 1) * 2 + 1]);
            }
        }
    }

    // ---- fused epilogue ----
    float pvR[4][2]; int piR[4][2];
    float pvC[4][2]; int piC[4][2];
    float sR[4][2], sC[4][2];
    int   cR[4][2], cC[4][2];
#pragma unroll
    for (int mt = 0; mt < 4; mt++)
#pragma unroll
        for (int h = 0; h < 2; h++) {
            int row = rowBase + warpM * 64 + mt * 16 + (l >> 2) + h * 8;
            pvR[mt][h] = g_pos[row]; piR[mt][h] = (row + HALF) & (N - 1);
            sR[mt][h] = 0.f; cR[mt][h] = 0;
        }
#pragma unroll
    for (int nt = 0; nt < 4; nt++)
#pragma unroll
        for (int e = 0; e < 2; e++) {
            int col = colBase + warpN * 32 + nt * 8 + (l & 3) * 2 + e;
            pvC[nt][e] = g_pos[col]; piC[nt][e] = (col + HALF) & (N - 1);
            sC[nt][e] = 0.f; cC[nt][e] = 0;
        }

#pragma unroll
    for (int mt = 0; mt < 4; mt++)
#pragma unroll
        for (int nt = 0; nt < 4; nt++)
#pragma unroll
            for (int r = 0; r < 4; r++) {
                const int h = r >> 1, e = r & 1;
                const int row = rowBase + warpM * 64 + mt * 16 + (l >> 2) + h * 8;
                const int col = colBase + warpN * 32 + nt * 8 + (l & 3) * 2 + e;
                const float sim = acc[mt][nt][r];
                const float ex  = __expf((sim - 1.0f) * invT);
                if (col != row) {
                    sR[mt][h] += ex;
                    if (col != piR[mt][h]) {
                        float d = sim - pvR[mt][h];
                        if (d > DELTA) cR[mt][h]++;
                        else if (d >= -DELTA) push_border(row, col);
                    }
                }
                if (offd) {
                    sC[nt][e] += ex;
                    if (row != piC[nt][e]) {
                        float d = sim - pvC[nt][e];
                        if (d > DELTA) cC[nt][e]++;
                        else if (d >= -DELTA) push_border(col, row);
                    }
                }
            }

#pragma unroll
    for (int mt = 0; mt < 4; mt++)
#pragma unroll
        for (int h = 0; h < 2; h++) {
            float s = sR[mt][h]; int c = cR[mt][h];
            s += __shfl_xor_sync(0xffffffffu, s, 1);
            s += __shfl_xor_sync(0xffffffffu, s, 2);
            c += __shfl_xor_sync(0xffffffffu, c, 1);
            c += __shfl_xor_sync(0xffffffffu, c, 2);
            if ((l & 3) == 0) {
                int row = rowBase + warpM * 64 + mt * 16 + (l >> 2) + h * 8;
                atomicAdd(&g_rowS[row], s);
                atomicAdd(&g_rowC[row], c);
            }
        }
    if (offd) {
#pragma unroll
        for (int nt = 0; nt < 4; nt++)
#pragma unroll
            for (int e = 0; e < 2; e++) {
                float s = sC[nt][e]; int c = cC[nt][e];
                s += __shfl_xor_sync(0xffffffffu, s, 4);
                s += __shfl_xor_sync(0xffffffffu, s, 8);
                s += __shfl_xor_sync(0xffffffffu, s, 16);
                c += __shfl_xor_sync(0xffffffffu, c, 4);
                c += __shfl_xor_sync(0xffffffffu, c, 8);
                c += __shfl_xor_sync(0xffffffffu, c, 16);
                if (l < 4) {
                    int col = colBase + warpN * 32 + nt * 8 + (l & 3) * 2 + e;
                    atomicAdd(&g_rowS[col], s);
                    atomicAdd(&g_rowC[col], c);
                }
            }
    }
}

// Flat exact recheck: one warp per borderline pair (L2-BW floor).
__global__ void k_recheck() {
    const int nWarps = gridDim.x * (blockDim.x >> 5);
    const int w      = blockIdx.x * (blockDim.x >> 5) + (threadIdx.x >> 5);
    const int lane   = threadIdx.x & 31;
    const int cnt    = min(g_nBorder, BCAP);
    for (int e = w; e < cnt; e += nWarps) {
        const uint32_t p = g_border[e];
        const int i = (int)(p >> 13);
        const int j = (int)(p & 8191u);
        const float4* a = reinterpret_cast<const float4*>(g_fn + (size_t)i * D);
        const float4* b = reinterpret_cast<const float4*>(g_fn + (size_t)j * D);
        float s = 0.f;
#pragma unroll
        for (int q = 0; q < 4; q++) {
            float4 x = a[lane + q * 32], y = b[lane + q * 32];
            s = fmaf(x.x, y.x, fmaf(x.y, y.y, fmaf(x.z, y.z, fmaf(x.w, y.w, s))));
        }
#pragma unroll
        for (int o = 16; o; o >>= 1) s += __shfl_xor_sync(0xffffffffu, s, o);
        if (lane == 0 && s > g_pos[i]) atomicAdd(&g_rowC[i], 1);
    }
}

// Per-row stats + global accumulate; last block writes the 4 outputs.
__global__ void k_merge(float* __restrict__ out) {
    const int row = blockIdx.x * 256 + threadIdx.x;
    const float invT = 1.0f / TEMP;
    const float sv = g_rowS[row];
    const int   cv = g_rowC[row];
    const float term = (logf(sv) + invT) - g_pos[row] * invT;
    float wterm = term;
    int wt1 = (cv == 0) ? 1 : 0;
    int wt5 = (cv < 5) ? 1 : 0;
    long long wr = cv;
#pragma unroll
    for (int o = 16; o; o >>= 1) {
        wterm += __shfl_xor_sync(0xffffffffu, wterm, o);
        wt1   += __shfl_xor_sync(0xffffffffu, wt1, o);
        wt5   += __shfl_xor_sync(0xffffffffu, wt5, o);
        wr    += __shfl_xor_sync(0xffffffffu, wr, o);
    }
    __shared__ double s_term[8];
    __shared__ int s_t1[8], s_t5[8];
    __shared__ unsigned long long s_r[8];
    const int lane = threadIdx.x & 31, w = threadIdx.x >> 5;
    if (lane == 0) { s_term[w] = (double)wterm; s_t1[w] = wt1; s_t5[w] = wt5; s_r[w] = (unsigned long long)wr; }
    __syncthreads();
    __shared__ int sIsLast;
    if (threadIdx.x == 0) {
        double a = 0.0; int b = 0, c = 0; unsigned long long d2 = 0ull;
#pragma unroll
        for (int i = 0; i < 8; i++) { a += s_term[i]; b += s_t1[i]; c += s_t5[i]; d2 += s_r[i]; }
        atomicAdd(&g_nll, a);
        atomicAdd(&g_top1, b);
        atomicAdd(&g_top5, c);
        atomicAdd(&g_rank, d2);
        __threadfence();
        sIsLast = (atomicAdd(&g_done, 1) == (int)gridDim.x - 1) ? 1 : 0;
    }
    __syncthreads();
    if (threadIdx.x == 0 && sIsLast) {
        __threadfence();
        out[0] = (float)(g_nll / (double)N);
        out[1] = (float)g_top1 / (float)N;
        out[2] = (float)g_top5 / (float)N;
        out[3] = 1.0f + (float)((double)g_rank / (double)N);
    }
}

extern "C" void kernel_launch(void* const* d_in, const int* in_sizes, int n_in,
                              void* d_out, int out_size) {
    (void)in_sizes; (void)n_in; (void)out_size;
    const float* f1 = (const float*)d_in[0];
    const float* f2 = (const float*)d_in[1];
    float* out = (float*)d_out;

    cudaFuncSetAttribute(k_main, cudaFuncAttributeMaxDynamicSharedMemorySize, SMEM_DYN);

    k_norm<<<N, 128>>>(f1, f2);
    k_pos<<<N / 8, 256>>>();
    k_main<<<NTILES, 256, SMEM_DYN>>>();
    k_recheck<<<REC_BLOCKS, 256>>>();
    k_merge<<<N / 256, 256>>>(out);
}